// round 15
// baseline (speedup 1.0000x reference)
#include <cuda_runtime.h>
#include <cuda_bf16.h>
#include <cuda.h>
#include <stdint.h>

#define NN 4096
#define DD 256
#define MARGIN 0.1f
#define EPS 0.002f

#if defined(__CUDA_ARCH_FEAT_SM103_ALL) || defined(__CUDA_ARCH_FEAT_SM100_ALL)
#define HAS_TCGEN05 1
#else
#define HAS_TCGEN05 0
#endif

// idesc kind::f16: dtype=F32, atype=btype=BF16, N=256, M=128 (cg1)
#define IDESC 0x08400490u

// tile geometry
#define TM 128
#define TN 256
#define TILES_X (NN / TN)            // 16
#define TILES_Y (NN / TM)            // 32
#define NTILES  (TILES_X * TILES_Y)  // 512
#define NCTA    148
#define NTHREADS 544                 // 16 consumer warps + 1 producer warp

// stage layout (bytes): Ahi 16K | Alo 16K | Bhi 32K | Blo 32K
#define ST_ALO   16384
#define ST_BHI   32768
#define ST_BLO   65536
#define ST_BYTES 98304
#define OFF_TMEMP  (2 * ST_BYTES)         // 196608
#define OFF_MB     (OFF_TMEMP + 16)       // 8 mbarriers
#define OFF_DC     (OFF_TMEMP + 128)      // 2 x 256 floats
#define SMEM_DYN   (OFF_DC + 2048 + 1024)

typedef unsigned long long u64;

// ---- device-global scratch ----
__device__ double g_vt_sum;
__device__ double g_tv_sum;
__device__ unsigned g_done;
__device__ int    g_cnt[NN];
__device__ float  g_diag[NN];
__device__ __align__(1024) __nv_bfloat16 g_Vhi[NN * DD];
__device__ __align__(1024) __nv_bfloat16 g_Vlo[NN * DD];
__device__ __align__(1024) __nv_bfloat16 g_Thi[NN * DD];
__device__ __align__(1024) __nv_bfloat16 g_Tlo[NN * DD];

// ======================= PTX helpers =======================
__device__ __forceinline__ uint32_t smem_u32(const void* p) {
    uint32_t a;
    asm("{ .reg .u64 t; cvta.to.shared.u64 t, %1; cvt.u32.u64 %0, t; }"
        : "=r"(a) : "l"(p));
    return a;
}

#define MBARRIER_INIT(addr, cnt) \
    asm volatile("mbarrier.init.shared.b64 [%0], %1;" \
        :: "r"((uint32_t)(addr)), "r"((uint32_t)(cnt)) : "memory")

#define MBARRIER_EXPECT_TX(addr, bytes) \
    asm volatile("mbarrier.arrive.expect_tx.shared.b64 _, [%0], %1;" \
        :: "r"((uint32_t)(addr)), "r"((uint32_t)(bytes)) : "memory")

#define MBARRIER_ARRIVE(addr) \
    asm volatile("mbarrier.arrive.shared.b64 _, [%0];" \
        :: "r"((uint32_t)(addr)) : "memory")

#define MBARRIER_WAIT_PARITY(addr, parity) do {                                   \
    uint32_t _mb = (uint32_t)(addr);                                              \
    uint32_t _ph = (uint32_t)(parity);                                            \
    uint32_t _done;                                                               \
    asm volatile("{\n\t.reg .pred p;\n\t"                                         \
        "mbarrier.try_wait.parity.acquire.cta.shared::cta.b64 p, [%1], %2;\n\t"   \
        "selp.b32 %0, 1, 0, p;\n\t}"                                              \
        : "=r"(_done) : "r"(_mb), "r"(_ph) : "memory");                           \
    if (!_done) {                                                                 \
        asm volatile("{\n\t.reg .pred P1;\n\t"                                    \
            "W_%=:\n\t"                                                           \
            "mbarrier.try_wait.parity.acquire.cta.shared::cta.b64 P1, [%0], %1, 0x989680;\n\t" \
            "@P1 bra.uni D_%=;\n\t"                                               \
            "bra.uni W_%=;\n\t"                                                   \
            "D_%=:\n\t}"                                                          \
            :: "r"(_mb), "r"(_ph) : "memory");                                    \
    }                                                                             \
} while (0)

#if HAS_TCGEN05
#define TCGEN05_ALLOC(res_addr, ncols) \
    asm volatile("tcgen05.alloc.cta_group::1.sync.aligned.shared::cta.b32 [%0], %1;" \
        :: "r"((uint32_t)(res_addr)), "r"((uint32_t)(ncols)) : "memory")
#define TCGEN05_RELINQ() \
    asm volatile("tcgen05.relinquish_alloc_permit.cta_group::1.sync.aligned;")
#define TCGEN05_DEALLOC(tmem, ncols) \
    asm volatile("tcgen05.dealloc.cta_group::1.sync.aligned.b32 %0, %1;" \
        :: "r"(tmem), "r"((uint32_t)(ncols)))
#define TCGEN05_COMMIT(mbar) \
    asm volatile("tcgen05.commit.cta_group::1.mbarrier::arrive::one.shared::cluster.b64 [%0];" \
        :: "r"((uint32_t)(mbar)) : "memory")
#define TCGEN05_FENCE_AFTER() \
    asm volatile("tcgen05.fence::after_thread_sync;" ::: "memory")
#define TCGEN05_FENCE_BEFORE() \
    asm volatile("tcgen05.fence::before_thread_sync;" ::: "memory")
#define TCGEN05_WAIT_LD() \
    asm volatile("tcgen05.wait::ld.sync.aligned;" ::: "memory")

#define TCGEN05_LD_X32(r, addr) \
    asm volatile("tcgen05.ld.sync.aligned.32x32b.x32.b32 " \
        "{%0, %1, %2, %3, %4, %5, %6, %7, %8, %9, %10, %11, %12, %13, %14, %15, " \
        " %16, %17, %18, %19, %20, %21, %22, %23, %24, %25, %26, %27, %28, %29, %30, %31}, [%32];" \
        : "=r"((r)[0]),  "=r"((r)[1]),  "=r"((r)[2]),  "=r"((r)[3]),  \
          "=r"((r)[4]),  "=r"((r)[5]),  "=r"((r)[6]),  "=r"((r)[7]),  \
          "=r"((r)[8]),  "=r"((r)[9]),  "=r"((r)[10]), "=r"((r)[11]), \
          "=r"((r)[12]), "=r"((r)[13]), "=r"((r)[14]), "=r"((r)[15]), \
          "=r"((r)[16]), "=r"((r)[17]), "=r"((r)[18]), "=r"((r)[19]), \
          "=r"((r)[20]), "=r"((r)[21]), "=r"((r)[22]), "=r"((r)[23]), \
          "=r"((r)[24]), "=r"((r)[25]), "=r"((r)[26]), "=r"((r)[27]), \
          "=r"((r)[28]), "=r"((r)[29]), "=r"((r)[30]), "=r"((r)[31]) \
        : "r"(addr))

// SW128 SMEM descriptor: layout=SW128(2), version=1, SBO=64, LBO=1
static __device__ __forceinline__ uint64_t make_desc(uint32_t addr) {
    const uint64_t BASE =
        (uint64_t(2)  << 61) | (uint64_t(1) << 46) |
        (uint64_t(64) << 32) | (uint64_t(1) << 16);
    return BASE | ((uint64_t)(addr >> 4) & 0x3FFF);
}

__device__ __forceinline__ void tma_ld_2d(uint32_t dst, const void* map,
                                          int cx, int cy, uint32_t mbar) {
    asm volatile(
        "cp.async.bulk.tensor.2d.shared::cta.global.tile.mbarrier::complete_tx::bytes "
        "[%0], [%1, {%2, %3}], [%4];"
        :: "r"(dst), "l"(map), "r"(cx), "r"(cy), "r"(mbar) : "memory");
}

__device__ __forceinline__ void mma_f16_ss(uint32_t d, uint64_t da, uint64_t db,
                                           uint32_t en) {
    asm volatile("{\n\t.reg .pred p;\n\tsetp.ne.u32 p, %4, 0;\n\t"
        "tcgen05.mma.cta_group::1.kind::f16 [%0], %1, %2, %3, {%5, %5, %5, %5}, p;\n\t}"
        :: "r"(d), "l"(da), "l"(db), "r"(IDESC), "r"(en), "r"(0u) : "memory");
}
#endif  // HAS_TCGEN05

// ---------------------------------------------------------------------------
__device__ __forceinline__ void split4(float4 a, uint2& h, uint2& l) {
    __nv_bfloat162 hxy = __floats2bfloat162_rn(a.x, a.y);
    __nv_bfloat162 hzw = __floats2bfloat162_rn(a.z, a.w);
    float2 fxy = __bfloat1622float2(hxy);
    float2 fzw = __bfloat1622float2(hzw);
    __nv_bfloat162 lxy = __floats2bfloat162_rn(a.x - fxy.x, a.y - fxy.y);
    __nv_bfloat162 lzw = __floats2bfloat162_rn(a.z - fzw.x, a.w - fzw.y);
    h.x = reinterpret_cast<unsigned&>(hxy);
    h.y = reinterpret_cast<unsigned&>(hzw);
    l.x = reinterpret_cast<unsigned&>(lxy);
    l.y = reinterpret_cast<unsigned&>(lzw);
}

// exact fp32 dot of row r of V with row c of T (2-way ILP)
__device__ float exact_dot(const float* __restrict__ V,
                           const float* __restrict__ T, int r, int c) {
    const float4* a4 = reinterpret_cast<const float4*>(V + (size_t)r * DD);
    const float4* b4 = reinterpret_cast<const float4*>(T + (size_t)c * DD);
    float e0 = 0.f, e1 = 0.f;
    #pragma unroll 8
    for (int k = 0; k < DD / 4; k += 2) {
        float4 x  = a4[k],     y  = b4[k];
        float4 x1 = a4[k + 1], y1 = b4[k + 1];
        e0 += x.x * y.x + x.y * y.y + x.z * y.z + x.w * y.w;
        e1 += x1.x * y1.x + x1.y * y1.y + x1.z * y1.z + x1.w * y1.w;
    }
    return e0 + e1;
}

// ---------------------------------------------------------------------------
// Kernel 1: fused init — bf16 hi/lo split, exact fp32 diag, zero counters.
// ---------------------------------------------------------------------------
__global__ void init_kernel(const float* __restrict__ V,
                            const float* __restrict__ T) {
    const int gtid = blockIdx.x * blockDim.x + threadIdx.x;
    const int row  = gtid >> 5;
    const int lane = gtid & 31;
    if (gtid == 0) { g_vt_sum = 0.0; g_tv_sum = 0.0; g_done = 0u; }
    if (row >= NN) return;

    const float4* v4 = reinterpret_cast<const float4*>(V + (size_t)row * DD);
    const float4* t4 = reinterpret_cast<const float4*>(T + (size_t)row * DD);
    uint2* vh = reinterpret_cast<uint2*>(g_Vhi + (size_t)row * DD);
    uint2* vl = reinterpret_cast<uint2*>(g_Vlo + (size_t)row * DD);
    uint2* th = reinterpret_cast<uint2*>(g_Thi + (size_t)row * DD);
    uint2* tl = reinterpret_cast<uint2*>(g_Tlo + (size_t)row * DD);

    float acc = 0.f;
    #pragma unroll
    for (int p = 0; p < 2; p++) {
        const int idx = lane + p * 32;
        float4 a = v4[idx];
        float4 b = t4[idx];
        acc += a.x * b.x + a.y * b.y + a.z * b.z + a.w * b.w;
        uint2 h, l;
        split4(a, h, l); vh[idx] = h; vl[idx] = l;
        split4(b, h, l); th[idx] = h; tl[idx] = l;
    }
    #pragma unroll
    for (int off = 16; off > 0; off >>= 1)
        acc += __shfl_down_sync(0xFFFFFFFFu, acc, off);
    if (lane == 0) { g_diag[row] = acc; g_cnt[row] = 0; }
}

// ---------------------------------------------------------------------------
// Kernel 2: persistent warp-specialized tcgen05 GEMM + ranking epilogue +
// last-CTA finalize. 148 CTAs x 544 threads.
//   warps 0-15 : epilogue consumers — warp w: TMEM subpartition w&3
//                (rows (w&3)*32+lane), columns [(w>>2)*64, +64)
//   warp 16    : producer (thread 512 issues TMA + MMA), software-pipelined:
//                refill of stage s(kk-1) is issued while MMA(kk) executes.
// TMEM: two 256-col fp32 accumulator buffers, alternating per tile.
// ---------------------------------------------------------------------------
__global__ __launch_bounds__(NTHREADS, 1)
void gemm_tc_kernel(const __grid_constant__ CUtensorMap mVhi,
                    const __grid_constant__ CUtensorMap mVlo,
                    const __grid_constant__ CUtensorMap mThi,
                    const __grid_constant__ CUtensorMap mTlo,
                    const float* __restrict__ V,
                    const float* __restrict__ T,
                    float* __restrict__ out) {
    extern __shared__ char smem_raw[];
    const uint32_t raw  = smem_u32(smem_raw);
    const uint32_t base = (raw + 1023) & ~1023u;
    char* gbase = smem_raw + (base - raw);

    const int tid  = threadIdx.x;
    const int lane = tid & 31;
    const int cta  = blockIdx.x;
    const int ntiles = (NTILES - cta + NCTA - 1) / NCTA;

    float vt = 0.f, tv = 0.f;

#if HAS_TCGEN05
    const int wid = tid >> 5;
    const uint32_t S_TMEMP = base + OFF_TMEMP;
    const uint32_t MB_FULL = base + OFF_MB;        // +0, +8
    const uint32_t MB_EMPT = base + OFF_MB + 16;   // +16, +24
    const uint32_t MB_RES  = base + OFF_MB + 32;   // +32, +40
    const uint32_t MB_EPI  = base + OFF_MB + 48;   // +48, +56
    float* s_mdc = reinterpret_cast<float*>(gbase + OFF_DC);  // 2 x 256 floats

    if (wid == 16) {
        TCGEN05_ALLOC(S_TMEMP, 512);
        TCGEN05_RELINQ();
    }
    if (tid == 0) {
        MBARRIER_INIT(MB_FULL + 0, 1);
        MBARRIER_INIT(MB_FULL + 8, 1);
        MBARRIER_INIT(MB_EMPT + 0, 1);
        MBARRIER_INIT(MB_EMPT + 8, 1);
        MBARRIER_INIT(MB_RES  + 0, 1);
        MBARRIER_INIT(MB_RES  + 8, 1);
        MBARRIER_INIT(MB_EPI  + 0, 16);
        MBARRIER_INIT(MB_EPI  + 8, 16);
    }
    __syncthreads();
    uint32_t tmem;
    asm volatile("ld.shared.b32 %0, [%1];" : "=r"(tmem) : "r"(S_TMEMP));

    if (tid == 512) {
        // ---------------- producer (software-pipelined) ----------------
        const int nchunks = ntiles * 4;

        auto issue_tma = [&](int kk) {
            const int lt    = kk >> 2;
            const int chunk = kk & 3;
            const int s     = kk & 1;
            const int tile  = cta + lt * NCTA;
            const int row0  = (tile >> 4) * TM;
            const int col0  = (tile & 15) * TN;
            const uint32_t st = base + s * ST_BYTES;
            const uint32_t fb = MB_FULL + s * 8;
            MBARRIER_EXPECT_TX(fb, ST_BYTES);
            tma_ld_2d(st +      0, &mVhi, chunk * 64, row0, fb);
            tma_ld_2d(st + ST_ALO, &mVlo, chunk * 64, row0, fb);
            tma_ld_2d(st + ST_BHI, &mThi, chunk * 64, col0, fb);
            tma_ld_2d(st + ST_BLO, &mTlo, chunk * 64, col0, fb);
        };

        issue_tma(0);
        if (nchunks > 1) issue_tma(1);

        for (int kk = 0; kk < nchunks; kk++) {
            const int s     = kk & 1;
            const int lt    = kk >> 2;
            const int chunk = kk & 3;
            const int buf   = lt & 1;
            const uint32_t st = base + s * ST_BYTES;
            const uint32_t dbuf = tmem + buf * 256;

            MBARRIER_WAIT_PARITY(MB_FULL + s * 8, (kk >> 1) & 1);
            if (chunk == 0 && lt >= 2)
                MBARRIER_WAIT_PARITY(MB_EPI + buf * 8, ((lt - 2) >> 1) & 1);

            const uint64_t dAhi = make_desc(st);
            const uint64_t dAlo = make_desc(st + ST_ALO);
            const uint64_t dBhi = make_desc(st + ST_BHI);
            const uint64_t dBlo = make_desc(st + ST_BLO);
            #pragma unroll
            for (int ks = 0; ks < 4; ks++)
                mma_f16_ss(dbuf, dAhi + ks * 2, dBhi + ks * 2,
                           (chunk == 0 && ks == 0) ? 0u : 1u);
            #pragma unroll
            for (int ks = 0; ks < 4; ks++)
                mma_f16_ss(dbuf, dAhi + ks * 2, dBlo + ks * 2, 1u);
            #pragma unroll
            for (int ks = 0; ks < 4; ks++)
                mma_f16_ss(dbuf, dAlo + ks * 2, dBhi + ks * 2, 1u);

            TCGEN05_COMMIT(MB_EMPT + s * 8);
            if (chunk == 3) TCGEN05_COMMIT(MB_RES + buf * 8);

            // refill the OTHER stage (consumed at kk-1) with chunk kk+1,
            // overlapping with MMA(kk) execution on the tensor pipe.
            if (kk >= 1 && kk + 1 < nchunks) {
                MBARRIER_WAIT_PARITY(MB_EMPT + (s ^ 1) * 8, ((kk - 1) >> 1) & 1);
                issue_tma(kk + 1);
            }
        }
    } else if (tid < 512) {
        // ---------------- consumers: 16 warps, branch-free hot loop --------
        const int w   = wid;          // 0..15
        const int sub = w & 3;        // TMEM subpartition == SMSP
        const int ch  = w >> 2;       // 64-column chunk 0..3
        for (int lt = 0; lt < ntiles; lt++) {
            const int buf  = lt & 1;
            const int tile = cta + lt * NCTA;
            const int row0 = (tile >> 4) * TM;
            const int col0 = (tile & 15) * TN;
            const int r    = row0 + sub * 32 + lane;
            const uint32_t dbuf = tmem + buf * 256 + ch * 64;
            float* mdc = s_mdc + buf * 256 + ch * 64;
            int cnt = 0;

            // prefetch diag values BEFORE the result wait (hide LDG latency)
            const float dr  = g_diag[r];
            const float mdr = MARGIN - dr;
            const float m0  = MARGIN - g_diag[col0 + ch * 64 + lane];
            const float m1  = MARGIN - g_diag[col0 + ch * 64 + 32 + lane];

            MBARRIER_WAIT_PARITY(MB_RES + buf * 8, (lt >> 1) & 1);
            TCGEN05_FENCE_AFTER();

            // self-written per warp (each warp reads only what it wrote)
            mdc[lane]      = m0;
            mdc[lane + 32] = m1;

            #pragma unroll 1
            for (int g = 0; g < 2; g++) {
                uint32_t dreg[32];
                TCGEN05_LD_X32(dreg, dbuf + g * 32);
                TCGEN05_WAIT_LD();
                uint32_t tiebits = 0u;
                #pragma unroll
                for (int j = 0; j < 32; j++) {
                    const float sv = __uint_as_float(dreg[j]);
                    const float diff = sv - dr;
                    vt += fmaxf(sv + mdr, 0.f);
                    tv += fmaxf(sv + mdc[g * 32 + j], 0.f);
                    cnt += (diff > EPS) ? 1 : 0;
                    tiebits |= (fabsf(diff) <= EPS) ? (1u << j) : 0u;
                }
                if (tiebits) {   // rare: diagonal element + true near-ties
                    do {
                        const int j = __ffs(tiebits) - 1;
                        tiebits &= tiebits - 1u;
                        const int c = col0 + ch * 64 + g * 32 + j;
                        if (c != r)
                            cnt += (exact_dot(V, T, r, c) > dr) ? 1 : 0;
                    } while (tiebits);
                }
            }
            TCGEN05_FENCE_BEFORE();
            if (lane == 0) MBARRIER_ARRIVE(MB_EPI + buf * 8);
            atomicAdd(&g_cnt[r], cnt);
        }
    }

    __syncthreads();
    if (wid == 16) TCGEN05_DEALLOC(tmem, 512);

#else  // ---------------- fallback: plain fp32 (not selected on GB300) -----
    (void)mVhi; (void)mVlo; (void)mThi; (void)mTlo;
    for (int lt = 0; lt < ntiles; lt++) {
        const int tile = cta + lt * NCTA;
        const int row0 = (tile >> 4) * TM;
        const int col0 = (tile & 15) * TN;
        if (tid < 128) {
            const int r = row0 + tid;
            const float dr = g_diag[r];
            int cnt = 0;
            for (int cc = 0; cc < TN; cc++) {
                const int c = col0 + cc;
                if (c == r) { vt += MARGIN; tv += MARGIN; continue; }
                float s = exact_dot(V, T, r, c);
                vt += fmaxf(0.f, MARGIN - dr + s);
                tv += fmaxf(0.f, MARGIN - g_diag[c] + s);
                cnt += (s > dr) ? 1 : 0;
            }
            atomicAdd(&g_cnt[r], cnt);
        }
    }
    __syncthreads();
#endif

    // loss reduction: one double atomic per warp
    #pragma unroll
    for (int off = 16; off > 0; off >>= 1) {
        vt += __shfl_down_sync(0xFFFFFFFFu, vt, off);
        tv += __shfl_down_sync(0xFFFFFFFFu, tv, off);
    }
    if (lane == 0) {
        atomicAdd(&g_vt_sum, (double)vt);
        atomicAdd(&g_tv_sum, (double)tv);
    }

    // ---- last-CTA finalize ----
    __shared__ unsigned s_last;
    __shared__ int rA[512], rB[512], rC[512], rD[512];
    __threadfence();
    __syncthreads();
    if (tid == 0) s_last = (atomicAdd(&g_done, 1u) == (unsigned)(NCTA - 1));
    __syncthreads();
    if (!s_last) return;

    if (tid < 512) {
        int c1 = 0, c5 = 0, c10 = 0, rs = 0;
        for (int i = tid; i < NN; i += 512) {
            int c = g_cnt[i];
            c1  += (c < 1);
            c5  += (c < 5);
            c10 += (c < 10);
            rs  += c;
        }
        rA[tid] = c1; rB[tid] = c5; rC[tid] = c10; rD[tid] = rs;
    }
    __syncthreads();
    for (int s = 256; s > 0; s >>= 1) {
        if (tid < s) {
            rA[tid] += rA[tid + s]; rB[tid] += rB[tid + s];
            rC[tid] += rC[tid + s]; rD[tid] += rD[tid + s];
        }
        __syncthreads();
    }
    if (tid == 0) {
        const double denom = (double)NN * (double)(NN - 1);
        const double diagfix = (double)NN * (double)MARGIN;  // diagonal hinge
        out[0] = (float)((g_vt_sum - diagfix) / denom);
        out[1] = (float)((g_tv_sum - diagfix) / denom);
        out[2] = (float)rA[0] / (float)NN;
        out[3] = (float)rB[0] / (float)NN;
        out[4] = (float)rC[0] / (float)NN;
        out[5] = (float)rD[0] / (float)NN;
    }
}

// ---------------------------------------------------------------------------
typedef CUresult (*EncodeFn)(CUtensorMap*, CUtensorMapDataType, unsigned int,
                             void*, const unsigned long long*,
                             const unsigned long long*, const unsigned int*,
                             const unsigned int*, CUtensorMapInterleave,
                             CUtensorMapSwizzle, CUtensorMapL2promotion,
                             CUtensorMapFloatOOBfill);

static void encode_map(EncodeFn enc, CUtensorMap* m, void* ptr, unsigned rows) {
    unsigned long long dims[2]    = {DD, NN};
    unsigned long long strides[1] = {DD * sizeof(__nv_bfloat16)};
    unsigned int box[2]           = {64, rows};
    unsigned int es[2]            = {1, 1};
    enc(m, CU_TENSOR_MAP_DATA_TYPE_BFLOAT16, 2, ptr, dims, strides, box, es,
        CU_TENSOR_MAP_INTERLEAVE_NONE, CU_TENSOR_MAP_SWIZZLE_128B,
        CU_TENSOR_MAP_L2_PROMOTION_L2_128B, CU_TENSOR_MAP_FLOAT_OOB_FILL_NONE);
}

extern "C" void kernel_launch(void* const* d_in, const int* in_sizes, int n_in,
                              void* d_out, int out_size) {
    (void)in_sizes; (void)n_in; (void)out_size;
    const float* V = (const float*)d_in[0];
    const float* T = (const float*)d_in[1];
    float* out = (float*)d_out;

    void *pVhi, *pVlo, *pThi, *pTlo;
    cudaGetSymbolAddress(&pVhi, g_Vhi);
    cudaGetSymbolAddress(&pVlo, g_Vlo);
    cudaGetSymbolAddress(&pThi, g_Thi);
    cudaGetSymbolAddress(&pTlo, g_Tlo);

    void* sym = nullptr;
    cudaDriverEntryPointQueryResult qr;
    cudaGetDriverEntryPointByVersion("cuTensorMapEncodeTiled", &sym, 12000,
                                     cudaEnableDefault, &qr);
    EncodeFn enc = (EncodeFn)sym;

    CUtensorMap mVhi, mVlo, mThi, mTlo;
    encode_map(enc, &mVhi, pVhi, TM);   // A tiles: 128 rows
    encode_map(enc, &mVlo, pVlo, TM);
    encode_map(enc, &mThi, pThi, TN);   // B tiles: 256 rows
    encode_map(enc, &mTlo, pTlo, TN);

    cudaFuncSetAttribute(gemm_tc_kernel,
                         cudaFuncAttributeMaxDynamicSharedMemorySize, SMEM_DYN);

    init_kernel<<<NN * 32 / 256, 256>>>(V, T);
    gemm_tc_kernel<<<NCTA, NTHREADS, SMEM_DYN>>>(
        mVhi, mVlo, mThi, mTlo, V, T, out);
}

// round 16
// speedup vs baseline: 1.0885x; 1.0885x over previous
#include <cuda_runtime.h>
#include <cuda_bf16.h>
#include <cuda.h>
#include <stdint.h>

#define NN 4096
#define DD 256
#define MARGIN 0.1f
#define EPS 0.002f

#if defined(__CUDA_ARCH_FEAT_SM103_ALL) || defined(__CUDA_ARCH_FEAT_SM100_ALL)
#define HAS_TCGEN05 1
#else
#define HAS_TCGEN05 0
#endif

// idesc kind::f16: dtype=F32, atype=btype=BF16, N=256, M=128 (cg1)
#define IDESC 0x08400490u

// tile geometry
#define TM 128
#define TN 256
#define TILES_X (NN / TN)            // 16
#define TILES_Y (NN / TM)            // 32
#define NTILES  (TILES_X * TILES_Y)  // 512
#define NCTA    148
#define NTHREADS 544                 // 16 consumer warps + 1 producer warp

// stage layout (bytes): Ahi 16K | Alo 16K | Bhi 32K | Blo 32K
#define ST_ALO   16384
#define ST_BHI   32768
#define ST_BLO   65536
#define ST_BYTES 98304
#define OFF_TMEMP  (2 * ST_BYTES)         // 196608
#define OFF_MB     (OFF_TMEMP + 16)       // 8 mbarriers
#define OFF_DC     (OFF_TMEMP + 128)      // 2 x 256 floats
#define SMEM_DYN   (OFF_DC + 2048 + 1024)

typedef unsigned long long u64;

// ---- device-global scratch ----
__device__ double g_vt_sum;
__device__ double g_tv_sum;
__device__ unsigned g_done;
__device__ int    g_cnt[NN];
__device__ float  g_diag[NN];
__device__ __align__(1024) __nv_bfloat16 g_Vhi[NN * DD];
__device__ __align__(1024) __nv_bfloat16 g_Vlo[NN * DD];
__device__ __align__(1024) __nv_bfloat16 g_Thi[NN * DD];
__device__ __align__(1024) __nv_bfloat16 g_Tlo[NN * DD];

// ======================= PTX helpers =======================
__device__ __forceinline__ uint32_t smem_u32(const void* p) {
    uint32_t a;
    asm("{ .reg .u64 t; cvta.to.shared.u64 t, %1; cvt.u32.u64 %0, t; }"
        : "=r"(a) : "l"(p));
    return a;
}

#define MBARRIER_INIT(addr, cnt) \
    asm volatile("mbarrier.init.shared.b64 [%0], %1;" \
        :: "r"((uint32_t)(addr)), "r"((uint32_t)(cnt)) : "memory")

#define MBARRIER_EXPECT_TX(addr, bytes) \
    asm volatile("mbarrier.arrive.expect_tx.shared.b64 _, [%0], %1;" \
        :: "r"((uint32_t)(addr)), "r"((uint32_t)(bytes)) : "memory")

#define MBARRIER_ARRIVE(addr) \
    asm volatile("mbarrier.arrive.shared.b64 _, [%0];" \
        :: "r"((uint32_t)(addr)) : "memory")

#define MBARRIER_WAIT_PARITY(addr, parity) do {                                   \
    uint32_t _mb = (uint32_t)(addr);                                              \
    uint32_t _ph = (uint32_t)(parity);                                            \
    uint32_t _done;                                                               \
    asm volatile("{\n\t.reg .pred p;\n\t"                                         \
        "mbarrier.try_wait.parity.acquire.cta.shared::cta.b64 p, [%1], %2;\n\t"   \
        "selp.b32 %0, 1, 0, p;\n\t}"                                              \
        : "=r"(_done) : "r"(_mb), "r"(_ph) : "memory");                           \
    if (!_done) {                                                                 \
        asm volatile("{\n\t.reg .pred P1;\n\t"                                    \
            "W_%=:\n\t"                                                           \
            "mbarrier.try_wait.parity.acquire.cta.shared::cta.b64 P1, [%0], %1, 0x989680;\n\t" \
            "@P1 bra.uni D_%=;\n\t"                                               \
            "bra.uni W_%=;\n\t"                                                   \
            "D_%=:\n\t}"                                                          \
            :: "r"(_mb), "r"(_ph) : "memory");                                    \
    }                                                                             \
} while (0)

#if HAS_TCGEN05
#define TCGEN05_ALLOC(res_addr, ncols) \
    asm volatile("tcgen05.alloc.cta_group::1.sync.aligned.shared::cta.b32 [%0], %1;" \
        :: "r"((uint32_t)(res_addr)), "r"((uint32_t)(ncols)) : "memory")
#define TCGEN05_RELINQ() \
    asm volatile("tcgen05.relinquish_alloc_permit.cta_group::1.sync.aligned;")
#define TCGEN05_DEALLOC(tmem, ncols) \
    asm volatile("tcgen05.dealloc.cta_group::1.sync.aligned.b32 %0, %1;" \
        :: "r"(tmem), "r"((uint32_t)(ncols)))
#define TCGEN05_COMMIT(mbar) \
    asm volatile("tcgen05.commit.cta_group::1.mbarrier::arrive::one.shared::cluster.b64 [%0];" \
        :: "r"((uint32_t)(mbar)) : "memory")
#define TCGEN05_FENCE_AFTER() \
    asm volatile("tcgen05.fence::after_thread_sync;" ::: "memory")
#define TCGEN05_FENCE_BEFORE() \
    asm volatile("tcgen05.fence::before_thread_sync;" ::: "memory")
#define TCGEN05_WAIT_LD() \
    asm volatile("tcgen05.wait::ld.sync.aligned;" ::: "memory")

#define TCGEN05_LD_X32(r, addr) \
    asm volatile("tcgen05.ld.sync.aligned.32x32b.x32.b32 " \
        "{%0, %1, %2, %3, %4, %5, %6, %7, %8, %9, %10, %11, %12, %13, %14, %15, " \
        " %16, %17, %18, %19, %20, %21, %22, %23, %24, %25, %26, %27, %28, %29, %30, %31}, [%32];" \
        : "=r"((r)[0]),  "=r"((r)[1]),  "=r"((r)[2]),  "=r"((r)[3]),  \
          "=r"((r)[4]),  "=r"((r)[5]),  "=r"((r)[6]),  "=r"((r)[7]),  \
          "=r"((r)[8]),  "=r"((r)[9]),  "=r"((r)[10]), "=r"((r)[11]), \
          "=r"((r)[12]), "=r"((r)[13]), "=r"((r)[14]), "=r"((r)[15]), \
          "=r"((r)[16]), "=r"((r)[17]), "=r"((r)[18]), "=r"((r)[19]), \
          "=r"((r)[20]), "=r"((r)[21]), "=r"((r)[22]), "=r"((r)[23]), \
          "=r"((r)[24]), "=r"((r)[25]), "=r"((r)[26]), "=r"((r)[27]), \
          "=r"((r)[28]), "=r"((r)[29]), "=r"((r)[30]), "=r"((r)[31]) \
        : "r"(addr))

// SW128 SMEM descriptor: layout=SW128(2), version=1, SBO=64, LBO=1
static __device__ __forceinline__ uint64_t make_desc(uint32_t addr) {
    const uint64_t BASE =
        (uint64_t(2)  << 61) | (uint64_t(1) << 46) |
        (uint64_t(64) << 32) | (uint64_t(1) << 16);
    return BASE | ((uint64_t)(addr >> 4) & 0x3FFF);
}

__device__ __forceinline__ void tma_ld_2d(uint32_t dst, const void* map,
                                          int cx, int cy, uint32_t mbar) {
    asm volatile(
        "cp.async.bulk.tensor.2d.shared::cta.global.tile.mbarrier::complete_tx::bytes "
        "[%0], [%1, {%2, %3}], [%4];"
        :: "r"(dst), "l"(map), "r"(cx), "r"(cy), "r"(mbar) : "memory");
}

__device__ __forceinline__ void mma_f16_ss(uint32_t d, uint64_t da, uint64_t db,
                                           uint32_t en) {
    asm volatile("{\n\t.reg .pred p;\n\tsetp.ne.u32 p, %4, 0;\n\t"
        "tcgen05.mma.cta_group::1.kind::f16 [%0], %1, %2, %3, {%5, %5, %5, %5}, p;\n\t}"
        :: "r"(d), "l"(da), "l"(db), "r"(IDESC), "r"(en), "r"(0u) : "memory");
}
#endif  // HAS_TCGEN05

// ---------------------------------------------------------------------------
__device__ __forceinline__ void split4(float4 a, uint2& h, uint2& l) {
    __nv_bfloat162 hxy = __floats2bfloat162_rn(a.x, a.y);
    __nv_bfloat162 hzw = __floats2bfloat162_rn(a.z, a.w);
    float2 fxy = __bfloat1622float2(hxy);
    float2 fzw = __bfloat1622float2(hzw);
    __nv_bfloat162 lxy = __floats2bfloat162_rn(a.x - fxy.x, a.y - fxy.y);
    __nv_bfloat162 lzw = __floats2bfloat162_rn(a.z - fzw.x, a.w - fzw.y);
    h.x = reinterpret_cast<unsigned&>(hxy);
    h.y = reinterpret_cast<unsigned&>(hzw);
    l.x = reinterpret_cast<unsigned&>(lxy);
    l.y = reinterpret_cast<unsigned&>(lzw);
}

// exact fp32 dot of row r of V with row c of T (2-way ILP)
__device__ float exact_dot(const float* __restrict__ V,
                           const float* __restrict__ T, int r, int c) {
    const float4* a4 = reinterpret_cast<const float4*>(V + (size_t)r * DD);
    const float4* b4 = reinterpret_cast<const float4*>(T + (size_t)c * DD);
    float e0 = 0.f, e1 = 0.f;
    #pragma unroll 8
    for (int k = 0; k < DD / 4; k += 2) {
        float4 x  = a4[k],     y  = b4[k];
        float4 x1 = a4[k + 1], y1 = b4[k + 1];
        e0 += x.x * y.x + x.y * y.y + x.z * y.z + x.w * y.w;
        e1 += x1.x * y1.x + x1.y * y1.y + x1.z * y1.z + x1.w * y1.w;
    }
    return e0 + e1;
}

// ---------------------------------------------------------------------------
// Kernel 1: fused init — bf16 hi/lo split, exact fp32 diag, zero counters.
// ---------------------------------------------------------------------------
__global__ void init_kernel(const float* __restrict__ V,
                            const float* __restrict__ T) {
    const int gtid = blockIdx.x * blockDim.x + threadIdx.x;
    const int row  = gtid >> 5;
    const int lane = gtid & 31;
    if (gtid == 0) { g_vt_sum = 0.0; g_tv_sum = 0.0; g_done = 0u; }
    if (row >= NN) return;

    const float4* v4 = reinterpret_cast<const float4*>(V + (size_t)row * DD);
    const float4* t4 = reinterpret_cast<const float4*>(T + (size_t)row * DD);
    uint2* vh = reinterpret_cast<uint2*>(g_Vhi + (size_t)row * DD);
    uint2* vl = reinterpret_cast<uint2*>(g_Vlo + (size_t)row * DD);
    uint2* th = reinterpret_cast<uint2*>(g_Thi + (size_t)row * DD);
    uint2* tl = reinterpret_cast<uint2*>(g_Tlo + (size_t)row * DD);

    float acc = 0.f;
    #pragma unroll
    for (int p = 0; p < 2; p++) {
        const int idx = lane + p * 32;
        float4 a = v4[idx];
        float4 b = t4[idx];
        acc += a.x * b.x + a.y * b.y + a.z * b.z + a.w * b.w;
        uint2 h, l;
        split4(a, h, l); vh[idx] = h; vl[idx] = l;
        split4(b, h, l); th[idx] = h; tl[idx] = l;
    }
    #pragma unroll
    for (int off = 16; off > 0; off >>= 1)
        acc += __shfl_down_sync(0xFFFFFFFFu, acc, off);
    if (lane == 0) { g_diag[row] = acc; g_cnt[row] = 0; }
}

// ---------------------------------------------------------------------------
// Kernel 2: persistent warp-specialized tcgen05 GEMM + ranking epilogue +
// last-CTA finalize. 148 CTAs x 544 threads.
//   warps 0-15 : epilogue consumers — warp w: TMEM subpartition w&3
//                (rows (w&3)*32+lane), columns [(w>>2)*64, +64)
//   warp 16    : producer (thread 512 issues TMA + MMA), R14 ordering.
// Epilogue: branch-free hot loop; EPI arrive moved to right after the last
// TMEM load of the buffer so MMA reuse overlaps the remaining arithmetic.
// ---------------------------------------------------------------------------
__global__ __launch_bounds__(NTHREADS, 1)
void gemm_tc_kernel(const __grid_constant__ CUtensorMap mVhi,
                    const __grid_constant__ CUtensorMap mVlo,
                    const __grid_constant__ CUtensorMap mThi,
                    const __grid_constant__ CUtensorMap mTlo,
                    const float* __restrict__ V,
                    const float* __restrict__ T,
                    float* __restrict__ out) {
    extern __shared__ char smem_raw[];
    const uint32_t raw  = smem_u32(smem_raw);
    const uint32_t base = (raw + 1023) & ~1023u;
    char* gbase = smem_raw + (base - raw);

    const int tid  = threadIdx.x;
    const int lane = tid & 31;
    const int cta  = blockIdx.x;
    const int ntiles = (NTILES - cta + NCTA - 1) / NCTA;

    float vt = 0.f, tv = 0.f;

#if HAS_TCGEN05
    const int wid = tid >> 5;
    const uint32_t S_TMEMP = base + OFF_TMEMP;
    const uint32_t MB_FULL = base + OFF_MB;        // +0, +8
    const uint32_t MB_EMPT = base + OFF_MB + 16;   // +16, +24
    const uint32_t MB_RES  = base + OFF_MB + 32;   // +32, +40
    const uint32_t MB_EPI  = base + OFF_MB + 48;   // +48, +56
    float* s_mdc = reinterpret_cast<float*>(gbase + OFF_DC);  // 2 x 256 floats

    if (wid == 16) {
        TCGEN05_ALLOC(S_TMEMP, 512);
        TCGEN05_RELINQ();
    }
    if (tid == 0) {
        MBARRIER_INIT(MB_FULL + 0, 1);
        MBARRIER_INIT(MB_FULL + 8, 1);
        MBARRIER_INIT(MB_EMPT + 0, 1);
        MBARRIER_INIT(MB_EMPT + 8, 1);
        MBARRIER_INIT(MB_RES  + 0, 1);
        MBARRIER_INIT(MB_RES  + 8, 1);
        MBARRIER_INIT(MB_EPI  + 0, 16);
        MBARRIER_INIT(MB_EPI  + 8, 16);
    }
    __syncthreads();
    uint32_t tmem;
    asm volatile("ld.shared.b32 %0, [%1];" : "=r"(tmem) : "r"(S_TMEMP));

    if (tid == 512) {
        // ---------------- producer (R14 ordering) ----------------
        const int nchunks = ntiles * 4;

        // stage-constant descriptors, hoisted
        uint64_t dAhi_s[2], dAlo_s[2], dBhi_s[2], dBlo_s[2];
        #pragma unroll
        for (int s = 0; s < 2; s++) {
            const uint32_t st = base + s * ST_BYTES;
            dAhi_s[s] = make_desc(st);
            dAlo_s[s] = make_desc(st + ST_ALO);
            dBhi_s[s] = make_desc(st + ST_BHI);
            dBlo_s[s] = make_desc(st + ST_BLO);
        }

        auto issue_tma = [&](int kk) {
            const int lt    = kk >> 2;
            const int chunk = kk & 3;
            const int s     = kk & 1;
            const int tile  = cta + lt * NCTA;
            const int row0  = (tile >> 4) * TM;
            const int col0  = (tile & 15) * TN;
            const uint32_t st = base + s * ST_BYTES;
            const uint32_t fb = MB_FULL + s * 8;
            MBARRIER_EXPECT_TX(fb, ST_BYTES);
            tma_ld_2d(st +      0, &mVhi, chunk * 64, row0, fb);
            tma_ld_2d(st + ST_ALO, &mVlo, chunk * 64, row0, fb);
            tma_ld_2d(st + ST_BHI, &mThi, chunk * 64, col0, fb);
            tma_ld_2d(st + ST_BLO, &mTlo, chunk * 64, col0, fb);
        };

        issue_tma(0);
        if (nchunks > 1) issue_tma(1);

        for (int kk = 0; kk < nchunks; kk++) {
            const int s     = kk & 1;
            const int lt    = kk >> 2;
            const int chunk = kk & 3;
            const int buf   = lt & 1;
            const uint32_t dbuf = tmem + buf * 256;

            MBARRIER_WAIT_PARITY(MB_FULL + s * 8, (kk >> 1) & 1);
            if (chunk == 0 && lt >= 2)
                MBARRIER_WAIT_PARITY(MB_EPI + buf * 8, ((lt - 2) >> 1) & 1);

            #pragma unroll
            for (int ks = 0; ks < 4; ks++)
                mma_f16_ss(dbuf, dAhi_s[s] + ks * 2, dBhi_s[s] + ks * 2,
                           (chunk == 0 && ks == 0) ? 0u : 1u);
            #pragma unroll
            for (int ks = 0; ks < 4; ks++)
                mma_f16_ss(dbuf, dAhi_s[s] + ks * 2, dBlo_s[s] + ks * 2, 1u);
            #pragma unroll
            for (int ks = 0; ks < 4; ks++)
                mma_f16_ss(dbuf, dAlo_s[s] + ks * 2, dBhi_s[s] + ks * 2, 1u);

            TCGEN05_COMMIT(MB_EMPT + s * 8);
            if (chunk == 3) TCGEN05_COMMIT(MB_RES + buf * 8);

            if (kk + 2 < nchunks) {
                MBARRIER_WAIT_PARITY(MB_EMPT + s * 8, (kk >> 1) & 1);
                issue_tma(kk + 2);
            }
        }
    } else if (tid < 512) {
        // ---------------- consumers: 16 warps, branch-free hot loop --------
        const int w   = wid;          // 0..15
        const int sub = w & 3;        // TMEM subpartition == SMSP
        const int ch  = w >> 2;       // 64-column chunk 0..3
        for (int lt = 0; lt < ntiles; lt++) {
            const int buf  = lt & 1;
            const int tile = cta + lt * NCTA;
            const int row0 = (tile >> 4) * TM;
            const int col0 = (tile & 15) * TN;
            const int r    = row0 + sub * 32 + lane;
            const uint32_t dbuf = tmem + buf * 256 + ch * 64;
            float* mdc = s_mdc + buf * 256 + ch * 64;
            int cnt = 0;

            // prefetch diag values BEFORE the result wait (hide LDG latency)
            const float dr  = g_diag[r];
            const float mdr = MARGIN - dr;
            const float m0  = MARGIN - g_diag[col0 + ch * 64 + lane];
            const float m1  = MARGIN - g_diag[col0 + ch * 64 + 32 + lane];

            MBARRIER_WAIT_PARITY(MB_RES + buf * 8, (lt >> 1) & 1);
            TCGEN05_FENCE_AFTER();

            // self-written per warp (each warp reads only what it wrote)
            mdc[lane]      = m0;
            mdc[lane + 32] = m1;

            #pragma unroll 1
            for (int g = 0; g < 2; g++) {
                uint32_t dreg[32];
                TCGEN05_LD_X32(dreg, dbuf + g * 32);
                TCGEN05_WAIT_LD();
                if (g == 1) {
                    // all TMEM reads of this buffer are complete — release it
                    // so the producer's next MMA overlaps remaining arithmetic
                    TCGEN05_FENCE_BEFORE();
                    if (lane == 0) MBARRIER_ARRIVE(MB_EPI + buf * 8);
                }
                uint32_t tiebits = 0u;
                #pragma unroll
                for (int j = 0; j < 32; j++) {
                    const float sv = __uint_as_float(dreg[j]);
                    const float diff = sv - dr;
                    vt += fmaxf(sv + mdr, 0.f);
                    tv += fmaxf(sv + mdc[g * 32 + j], 0.f);
                    cnt += (diff > EPS) ? 1 : 0;
                    tiebits |= (fabsf(diff) <= EPS) ? (1u << j) : 0u;
                }
                if (tiebits) {   // rare: diagonal element + true near-ties
                    do {
                        const int j = __ffs(tiebits) - 1;
                        tiebits &= tiebits - 1u;
                        const int c = col0 + ch * 64 + g * 32 + j;
                        if (c != r)
                            cnt += (exact_dot(V, T, r, c) > dr) ? 1 : 0;
                    } while (tiebits);
                }
            }
            atomicAdd(&g_cnt[r], cnt);
        }
    }

    __syncthreads();
    if (wid == 16) TCGEN05_DEALLOC(tmem, 512);

#else  // ---------------- fallback: plain fp32 (not selected on GB300) -----
    (void)mVhi; (void)mVlo; (void)mThi; (void)mTlo;
    for (int lt = 0; lt < ntiles; lt++) {
        const int tile = cta + lt * NCTA;
        const int row0 = (tile >> 4) * TM;
        const int col0 = (tile & 15) * TN;
        if (tid < 128) {
            const int r = row0 + tid;
            const float dr = g_diag[r];
            int cnt = 0;
            for (int cc = 0; cc < TN; cc++) {
                const int c = col0 + cc;
                if (c == r) { vt += MARGIN; tv += MARGIN; continue; }
                float s = exact_dot(V, T, r, c);
                vt += fmaxf(0.f, MARGIN - dr + s);
                tv += fmaxf(0.f, MARGIN - g_diag[c] + s);
                cnt += (s > dr) ? 1 : 0;
            }
            atomicAdd(&g_cnt[r], cnt);
        }
    }
    __syncthreads();
#endif

    // loss reduction: one double atomic per warp
    #pragma unroll
    for (int off = 16; off > 0; off >>= 1) {
        vt += __shfl_down_sync(0xFFFFFFFFu, vt, off);
        tv += __shfl_down_sync(0xFFFFFFFFu, tv, off);
    }
    if (lane == 0) {
        atomicAdd(&g_vt_sum, (double)vt);
        atomicAdd(&g_tv_sum, (double)tv);
    }

    // ---- last-CTA finalize ----
    __shared__ unsigned s_last;
    __shared__ int rA[512], rB[512], rC[512], rD[512];
    __threadfence();
    __syncthreads();
    if (tid == 0) s_last = (atomicAdd(&g_done, 1u) == (unsigned)(NCTA - 1));
    __syncthreads();
    if (!s_last) return;

    if (tid < 512) {
        int c1 = 0, c5 = 0, c10 = 0, rs = 0;
        for (int i = tid; i < NN; i += 512) {
            int c = g_cnt[i];
            c1  += (c < 1);
            c5  += (c < 5);
            c10 += (c < 10);
            rs  += c;
        }
        rA[tid] = c1; rB[tid] = c5; rC[tid] = c10; rD[tid] = rs;
    }
    __syncthreads();
    for (int s = 256; s > 0; s >>= 1) {
        if (tid < s) {
            rA[tid] += rA[tid + s]; rB[tid] += rB[tid + s];
            rC[tid] += rC[tid + s]; rD[tid] += rD[tid + s];
        }
        __syncthreads();
    }
    if (tid == 0) {
        const double denom = (double)NN * (double)(NN - 1);
        const double diagfix = (double)NN * (double)MARGIN;  // diagonal hinge
        out[0] = (float)((g_vt_sum - diagfix) / denom);
        out[1] = (float)((g_tv_sum - diagfix) / denom);
        out[2] = (float)rA[0] / (float)NN;
        out[3] = (float)rB[0] / (float)NN;
        out[4] = (float)rC[0] / (float)NN;
        out[5] = (float)rD[0] / (float)NN;
    }
}

// ---------------------------------------------------------------------------
typedef CUresult (*EncodeFn)(CUtensorMap*, CUtensorMapDataType, unsigned int,
                             void*, const unsigned long long*,
                             const unsigned long long*, const unsigned int*,
                             const unsigned int*, CUtensorMapInterleave,
                             CUtensorMapSwizzle, CUtensorMapL2promotion,
                             CUtensorMapFloatOOBfill);

static void encode_map(EncodeFn enc, CUtensorMap* m, void* ptr, unsigned rows) {
    unsigned long long dims[2]    = {DD, NN};
    unsigned long long strides[1] = {DD * sizeof(__nv_bfloat16)};
    unsigned int box[2]           = {64, rows};
    unsigned int es[2]            = {1, 1};
    enc(m, CU_TENSOR_MAP_DATA_TYPE_BFLOAT16, 2, ptr, dims, strides, box, es,
        CU_TENSOR_MAP_INTERLEAVE_NONE, CU_TENSOR_MAP_SWIZZLE_128B,
        CU_TENSOR_MAP_L2_PROMOTION_L2_128B, CU_TENSOR_MAP_FLOAT_OOB_FILL_NONE);
}

extern "C" void kernel_launch(void* const* d_in, const int* in_sizes, int n_in,
                              void* d_out, int out_size) {
    (void)in_sizes; (void)n_in; (void)out_size;
    const float* V = (const float*)d_in[0];
    const float* T = (const float*)d_in[1];
    float* out = (float*)d_out;

    void *pVhi, *pVlo, *pThi, *pTlo;
    cudaGetSymbolAddress(&pVhi, g_Vhi);
    cudaGetSymbolAddress(&pVlo, g_Vlo);
    cudaGetSymbolAddress(&pThi, g_Thi);
    cudaGetSymbolAddress(&pTlo, g_Tlo);

    void* sym = nullptr;
    cudaDriverEntryPointQueryResult qr;
    cudaGetDriverEntryPointByVersion("cuTensorMapEncodeTiled", &sym, 12000,
                                     cudaEnableDefault, &qr);
    EncodeFn enc = (EncodeFn)sym;

    CUtensorMap mVhi, mVlo, mThi, mTlo;
    encode_map(enc, &mVhi, pVhi, TM);   // A tiles: 128 rows
    encode_map(enc, &mVlo, pVlo, TM);
    encode_map(enc, &mThi, pThi, TN);   // B tiles: 256 rows
    encode_map(enc, &mTlo, pTlo, TN);

    cudaFuncSetAttribute(gemm_tc_kernel,
                         cudaFuncAttributeMaxDynamicSharedMemorySize, SMEM_DYN);

    init_kernel<<<NN * 32 / 256, 256>>>(V, T);
    gemm_tc_kernel<<<NCTA, NTHREADS, SMEM_DYN>>>(
        mVhi, mVlo, mThi, mTlo, V, T, out);
}

// round 17
// speedup vs baseline: 1.0949x; 1.0059x over previous
#include <cuda_runtime.h>
#include <cuda_bf16.h>
#include <cuda.h>
#include <stdint.h>

#define NN 4096
#define DD 256
#define MARGIN 0.1f
#define EPS 0.002f

#if defined(__CUDA_ARCH_FEAT_SM103_ALL) || defined(__CUDA_ARCH_FEAT_SM100_ALL)
#define HAS_TCGEN05 1
#else
#define HAS_TCGEN05 0
#endif

// idesc kind::f16: dtype=F32, atype=btype=BF16, N=256, M=128 (cg1)
#define IDESC 0x08400490u

// tile geometry
#define TM 128
#define TN 256
#define TILES_X (NN / TN)            // 16
#define TILES_Y (NN / TM)            // 32
#define NTILES  (TILES_X * TILES_Y)  // 512
#define NCTA    148
#define NPAIR   (NCTA / 2)           // 74
#define NQ      (NTILES / 2)         // 256 q-slots (each q = 2 tiles, one per rank)
#define NTHREADS 544                 // 16 consumer warps + 1 producer warp

// stage layout (bytes): Ahi 16K | Alo 16K | Bhi 32K | Blo 32K
#define ST_ALO   16384
#define ST_BHI   32768
#define ST_BLO   65536
#define ST_BYTES 98304
#define OFF_TMEMP  (2 * ST_BYTES)         // 196608
#define OFF_MB     (OFF_TMEMP + 16)       // mbarriers
#define OFF_DC     (OFF_TMEMP + 128)      // 2 x 256 floats
#define SMEM_DYN   (OFF_DC + 2048 + 1024)

typedef unsigned long long u64;

// ---- device-global scratch ----
__device__ double g_vt_sum;
__device__ double g_tv_sum;
__device__ unsigned g_done;
__device__ int    g_cnt[NN];
__device__ float  g_diag[NN];
__device__ __align__(1024) __nv_bfloat16 g_Vhi[NN * DD];
__device__ __align__(1024) __nv_bfloat16 g_Vlo[NN * DD];
__device__ __align__(1024) __nv_bfloat16 g_Thi[NN * DD];
__device__ __align__(1024) __nv_bfloat16 g_Tlo[NN * DD];

// ======================= PTX helpers =======================
__device__ __forceinline__ uint32_t smem_u32(const void* p) {
    uint32_t a;
    asm("{ .reg .u64 t; cvta.to.shared.u64 t, %1; cvt.u32.u64 %0, t; }"
        : "=r"(a) : "l"(p));
    return a;
}

#define MBARRIER_INIT(addr, cnt) \
    asm volatile("mbarrier.init.shared.b64 [%0], %1;" \
        :: "r"((uint32_t)(addr)), "r"((uint32_t)(cnt)) : "memory")

#define MBARRIER_EXPECT_TX(addr, bytes) \
    asm volatile("mbarrier.arrive.expect_tx.shared.b64 _, [%0], %1;" \
        :: "r"((uint32_t)(addr)), "r"((uint32_t)(bytes)) : "memory")

#define MBARRIER_ARRIVE(addr) \
    asm volatile("mbarrier.arrive.shared.b64 _, [%0];" \
        :: "r"((uint32_t)(addr)) : "memory")

#define MBARRIER_ARRIVE_CLUSTER(local_addr, target_rank) \
    asm volatile("{\n\t.reg .b32 ra;\n\t" \
        "mapa.shared::cluster.u32 ra, %0, %1;\n\t" \
        "mbarrier.arrive.shared::cluster.b64 _, [ra];\n\t}" \
        :: "r"((uint32_t)(local_addr)), "r"((uint32_t)(target_rank)) : "memory")

#define MBARRIER_WAIT_PARITY(addr, parity) do {                                   \
    uint32_t _mb = (uint32_t)(addr);                                              \
    uint32_t _ph = (uint32_t)(parity);                                            \
    uint32_t _done;                                                               \
    asm volatile("{\n\t.reg .pred p;\n\t"                                         \
        "mbarrier.try_wait.parity.acquire.cta.shared::cta.b64 p, [%1], %2;\n\t"   \
        "selp.b32 %0, 1, 0, p;\n\t}"                                              \
        : "=r"(_done) : "r"(_mb), "r"(_ph) : "memory");                           \
    if (!_done) {                                                                 \
        asm volatile("{\n\t.reg .pred P1;\n\t"                                    \
            "W_%=:\n\t"                                                           \
            "mbarrier.try_wait.parity.acquire.cta.shared::cta.b64 P1, [%0], %1, 0x989680;\n\t" \
            "@P1 bra.uni D_%=;\n\t"                                               \
            "bra.uni W_%=;\n\t"                                                   \
            "D_%=:\n\t}"                                                          \
            :: "r"(_mb), "r"(_ph) : "memory");                                    \
    }                                                                             \
} while (0)

#define CLUSTER_SYNC() do { \
    asm volatile("barrier.cluster.arrive.aligned;" ::: "memory"); \
    asm volatile("barrier.cluster.wait.aligned;" ::: "memory"); \
} while (0)

#if HAS_TCGEN05
#define TCGEN05_ALLOC(res_addr, ncols) \
    asm volatile("tcgen05.alloc.cta_group::1.sync.aligned.shared::cta.b32 [%0], %1;" \
        :: "r"((uint32_t)(res_addr)), "r"((uint32_t)(ncols)) : "memory")
#define TCGEN05_RELINQ() \
    asm volatile("tcgen05.relinquish_alloc_permit.cta_group::1.sync.aligned;")
#define TCGEN05_DEALLOC(tmem, ncols) \
    asm volatile("tcgen05.dealloc.cta_group::1.sync.aligned.b32 %0, %1;" \
        :: "r"(tmem), "r"((uint32_t)(ncols)))
#define TCGEN05_COMMIT(mbar) \
    asm volatile("tcgen05.commit.cta_group::1.mbarrier::arrive::one.shared::cluster.b64 [%0];" \
        :: "r"((uint32_t)(mbar)) : "memory")
#define TCGEN05_FENCE_AFTER() \
    asm volatile("tcgen05.fence::after_thread_sync;" ::: "memory")
#define TCGEN05_FENCE_BEFORE() \
    asm volatile("tcgen05.fence::before_thread_sync;" ::: "memory")
#define TCGEN05_WAIT_LD() \
    asm volatile("tcgen05.wait::ld.sync.aligned;" ::: "memory")

#define TCGEN05_LD_X32(r, addr) \
    asm volatile("tcgen05.ld.sync.aligned.32x32b.x32.b32 " \
        "{%0, %1, %2, %3, %4, %5, %6, %7, %8, %9, %10, %11, %12, %13, %14, %15, " \
        " %16, %17, %18, %19, %20, %21, %22, %23, %24, %25, %26, %27, %28, %29, %30, %31}, [%32];" \
        : "=r"((r)[0]),  "=r"((r)[1]),  "=r"((r)[2]),  "=r"((r)[3]),  \
          "=r"((r)[4]),  "=r"((r)[5]),  "=r"((r)[6]),  "=r"((r)[7]),  \
          "=r"((r)[8]),  "=r"((r)[9]),  "=r"((r)[10]), "=r"((r)[11]), \
          "=r"((r)[12]), "=r"((r)[13]), "=r"((r)[14]), "=r"((r)[15]), \
          "=r"((r)[16]), "=r"((r)[17]), "=r"((r)[18]), "=r"((r)[19]), \
          "=r"((r)[20]), "=r"((r)[21]), "=r"((r)[22]), "=r"((r)[23]), \
          "=r"((r)[24]), "=r"((r)[25]), "=r"((r)[26]), "=r"((r)[27]), \
          "=r"((r)[28]), "=r"((r)[29]), "=r"((r)[30]), "=r"((r)[31]) \
        : "r"(addr))

// SW128 SMEM descriptor: layout=SW128(2), version=1, SBO=64, LBO=1
static __device__ __forceinline__ uint64_t make_desc(uint32_t addr) {
    const uint64_t BASE =
        (uint64_t(2)  << 61) | (uint64_t(1) << 46) |
        (uint64_t(64) << 32) | (uint64_t(1) << 16);
    return BASE | ((uint64_t)(addr >> 4) & 0x3FFF);
}

__device__ __forceinline__ void tma_ld_2d(uint32_t dst, const void* map,
                                          int cx, int cy, uint32_t mbar) {
    asm volatile(
        "cp.async.bulk.tensor.2d.shared::cta.global.tile.mbarrier::complete_tx::bytes "
        "[%0], [%1, {%2, %3}], [%4];"
        :: "r"(dst), "l"(map), "r"(cx), "r"(cy), "r"(mbar) : "memory");
}

__device__ __forceinline__ void tma_ld_2d_mc(uint32_t dst, const void* map,
                                             int cx, int cy, uint32_t mbar,
                                             uint16_t mask) {
    asm volatile(
        "cp.async.bulk.tensor.2d.shared::cluster.global.tile.mbarrier::complete_tx::bytes.multicast::cluster "
        "[%0], [%1, {%2, %3}], [%4], %5;"
        :: "r"(dst), "l"(map), "r"(cx), "r"(cy), "r"(mbar), "h"(mask) : "memory");
}

__device__ __forceinline__ void mma_f16_ss(uint32_t d, uint64_t da, uint64_t db,
                                           uint32_t en) {
    asm volatile("{\n\t.reg .pred p;\n\tsetp.ne.u32 p, %4, 0;\n\t"
        "tcgen05.mma.cta_group::1.kind::f16 [%0], %1, %2, %3, {%5, %5, %5, %5}, p;\n\t}"
        :: "r"(d), "l"(da), "l"(db), "r"(IDESC), "r"(en), "r"(0u) : "memory");
}
#endif  // HAS_TCGEN05

// ---------------------------------------------------------------------------
__device__ __forceinline__ void split4(float4 a, uint2& h, uint2& l) {
    __nv_bfloat162 hxy = __floats2bfloat162_rn(a.x, a.y);
    __nv_bfloat162 hzw = __floats2bfloat162_rn(a.z, a.w);
    float2 fxy = __bfloat1622float2(hxy);
    float2 fzw = __bfloat1622float2(hzw);
    __nv_bfloat162 lxy = __floats2bfloat162_rn(a.x - fxy.x, a.y - fxy.y);
    __nv_bfloat162 lzw = __floats2bfloat162_rn(a.z - fzw.x, a.w - fzw.y);
    h.x = reinterpret_cast<unsigned&>(hxy);
    h.y = reinterpret_cast<unsigned&>(hzw);
    l.x = reinterpret_cast<unsigned&>(lxy);
    l.y = reinterpret_cast<unsigned&>(lzw);
}

// exact fp32 dot of row r of V with row c of T (2-way ILP)
__device__ float exact_dot(const float* __restrict__ V,
                           const float* __restrict__ T, int r, int c) {
    const float4* a4 = reinterpret_cast<const float4*>(V + (size_t)r * DD);
    const float4* b4 = reinterpret_cast<const float4*>(T + (size_t)c * DD);
    float e0 = 0.f, e1 = 0.f;
    #pragma unroll 8
    for (int k = 0; k < DD / 4; k += 2) {
        float4 x  = a4[k],     y  = b4[k];
        float4 x1 = a4[k + 1], y1 = b4[k + 1];
        e0 += x.x * y.x + x.y * y.y + x.z * y.z + x.w * y.w;
        e1 += x1.x * y1.x + x1.y * y1.y + x1.z * y1.z + x1.w * y1.w;
    }
    return e0 + e1;
}

// ---------------------------------------------------------------------------
// Kernel 1: fused init — bf16 hi/lo split, exact fp32 diag, zero counters.
// ---------------------------------------------------------------------------
__global__ void init_kernel(const float* __restrict__ V,
                            const float* __restrict__ T) {
    const int gtid = blockIdx.x * blockDim.x + threadIdx.x;
    const int row  = gtid >> 5;
    const int lane = gtid & 31;
    if (gtid == 0) { g_vt_sum = 0.0; g_tv_sum = 0.0; g_done = 0u; }
    if (row >= NN) return;

    const float4* v4 = reinterpret_cast<const float4*>(V + (size_t)row * DD);
    const float4* t4 = reinterpret_cast<const float4*>(T + (size_t)row * DD);
    uint2* vh = reinterpret_cast<uint2*>(g_Vhi + (size_t)row * DD);
    uint2* vl = reinterpret_cast<uint2*>(g_Vlo + (size_t)row * DD);
    uint2* th = reinterpret_cast<uint2*>(g_Thi + (size_t)row * DD);
    uint2* tl = reinterpret_cast<uint2*>(g_Tlo + (size_t)row * DD);

    float acc = 0.f;
    #pragma unroll
    for (int p = 0; p < 2; p++) {
        const int idx = lane + p * 32;
        float4 a = v4[idx];
        float4 b = t4[idx];
        acc += a.x * b.x + a.y * b.y + a.z * b.z + a.w * b.w;
        uint2 h, l;
        split4(a, h, l); vh[idx] = h; vl[idx] = l;
        split4(b, h, l); th[idx] = h; tl[idx] = l;
    }
    #pragma unroll
    for (int off = 16; off > 0; off >>= 1)
        acc += __shfl_down_sync(0xFFFFFFFFu, acc, off);
    if (lane == 0) { g_diag[row] = acc; g_cnt[row] = 0; }
}

// ---------------------------------------------------------------------------
// Kernel 2: persistent warp-specialized tcgen05 GEMM + ranking epilogue +
// last-CTA finalize. 148 CTAs (74 clusters of 2) x 544 threads.
// Cluster pairs share col0 (B operand); B hi/lo is TMA-multicast by an
// alternating issuer rank, halving avg per-SM TMA engine rows.
// Tile map: q = pair + lt*74 (q < 256); row0 = ((q>>4)*2 + rank)*TM,
// col0 = (q&15)*TN.
//   warps 0-15 : epilogue consumers; warp 16: producer (thread 512).
// ---------------------------------------------------------------------------
__global__ __launch_bounds__(NTHREADS, 1)
#if HAS_TCGEN05 || (__CUDA_ARCH__ >= 900)
__cluster_dims__(2, 1, 1)
#endif
void gemm_tc_kernel(const __grid_constant__ CUtensorMap mVhi,
                    const __grid_constant__ CUtensorMap mVlo,
                    const __grid_constant__ CUtensorMap mThi,
                    const __grid_constant__ CUtensorMap mTlo,
                    const float* __restrict__ V,
                    const float* __restrict__ T,
                    float* __restrict__ out) {
    extern __shared__ char smem_raw[];
    const uint32_t raw  = smem_u32(smem_raw);
    const uint32_t base = (raw + 1023) & ~1023u;
    char* gbase = smem_raw + (base - raw);

    const int tid  = threadIdx.x;
    const int lane = tid & 31;
    const int cta  = blockIdx.x;
    const int pair = cta >> 1;
    const int rank = cta & 1;
    const int ntiles = (NQ - pair + NPAIR - 1) / NPAIR;  // 4 for pair<34 else 3

    float vt = 0.f, tv = 0.f;

#if HAS_TCGEN05
    const int wid = tid >> 5;
    const uint32_t S_TMEMP = base + OFF_TMEMP;
    const uint32_t MB_FULL  = base + OFF_MB;        // +0, +8
    const uint32_t MB_EMPT  = base + OFF_MB + 16;   // +16, +24
    const uint32_t MB_RES   = base + OFF_MB + 32;   // +32, +40
    const uint32_t MB_EPI   = base + OFF_MB + 48;   // +48, +56
    const uint32_t MB_EMPTX = base + OFF_MB + 64;   // +64, +72 (peer-freed)
    float* s_mdc = reinterpret_cast<float*>(gbase + OFF_DC);  // 2 x 256 floats

    if (wid == 16) {
        TCGEN05_ALLOC(S_TMEMP, 512);
        TCGEN05_RELINQ();
    }
    if (tid == 0) {
        MBARRIER_INIT(MB_FULL  + 0, 1);
        MBARRIER_INIT(MB_FULL  + 8, 1);
        MBARRIER_INIT(MB_EMPT  + 0, 1);
        MBARRIER_INIT(MB_EMPT  + 8, 1);
        MBARRIER_INIT(MB_RES   + 0, 1);
        MBARRIER_INIT(MB_RES   + 8, 1);
        MBARRIER_INIT(MB_EPI   + 0, 16);
        MBARRIER_INIT(MB_EPI   + 8, 16);
        MBARRIER_INIT(MB_EMPTX + 0, 1);
        MBARRIER_INIT(MB_EMPTX + 8, 1);
    }
    __syncthreads();
    CLUSTER_SYNC();     // peer mbarriers live before any multicast targets them
    uint32_t tmem;
    asm volatile("ld.shared.b32 %0, [%1];" : "=r"(tmem) : "r"(S_TMEMP));

    if (tid == 512) {
        // ---------------- producer ----------------
        const int nchunks = ntiles * 4;

        auto issue_fill = [&](int kk) {
            const int lt    = kk >> 2;
            const int chunk = kk & 3;
            const int s     = kk & 1;
            const int q     = pair + lt * NPAIR;
            const int row0  = ((q >> 4) * 2 + rank) * TM;
            const int col0  = (q & 15) * TN;
            const uint32_t st = base + s * ST_BYTES;
            const uint32_t fb = MB_FULL + s * 8;
            MBARRIER_EXPECT_TX(fb, ST_BYTES);
            tma_ld_2d(st +      0, &mVhi, chunk * 64, row0, fb);
            tma_ld_2d(st + ST_ALO, &mVlo, chunk * 64, row0, fb);
            if (rank == (kk & 1)) {
                // multicast B hi/lo to both CTAs of the cluster
                tma_ld_2d_mc(st + ST_BHI, &mThi, chunk * 64, col0, fb, 3);
                tma_ld_2d_mc(st + ST_BLO, &mTlo, chunk * 64, col0, fb, 3);
            }
        };

        issue_fill(0);
        if (nchunks > 1) issue_fill(1);

        for (int kk = 0; kk < nchunks; kk++) {
            const int s     = kk & 1;
            const int lt    = kk >> 2;
            const int chunk = kk & 3;
            const int buf   = lt & 1;
            const uint32_t st   = base + s * ST_BYTES;
            const uint32_t dbuf = tmem + buf * 256;

            MBARRIER_WAIT_PARITY(MB_FULL + s * 8, (kk >> 1) & 1);
            if (chunk == 0 && lt >= 2)
                MBARRIER_WAIT_PARITY(MB_EPI + buf * 8, ((lt - 2) >> 1) & 1);

            const uint64_t dAhi = make_desc(st);
            const uint64_t dAlo = make_desc(st + ST_ALO);
            const uint64_t dBhi = make_desc(st + ST_BHI);
            const uint64_t dBlo = make_desc(st + ST_BLO);
            #pragma unroll
            for (int ks = 0; ks < 4; ks++)
                mma_f16_ss(dbuf, dAhi + ks * 2, dBhi + ks * 2,
                           (chunk == 0 && ks == 0) ? 0u : 1u);
            #pragma unroll
            for (int ks = 0; ks < 4; ks++)
                mma_f16_ss(dbuf, dAhi + ks * 2, dBlo + ks * 2, 1u);
            #pragma unroll
            for (int ks = 0; ks < 4; ks++)
                mma_f16_ss(dbuf, dAlo + ks * 2, dBhi + ks * 2, 1u);

            TCGEN05_COMMIT(MB_EMPT + s * 8);
            if (chunk == 3) TCGEN05_COMMIT(MB_RES + buf * 8);

            if (kk + 2 < nchunks) {
                // stage s free locally (our MMAs done)...
                MBARRIER_WAIT_PARITY(MB_EMPT + s * 8, (kk >> 1) & 1);
                // ...tell peer, and wait until peer also freed its stage s,
                // so the B multicast can't overwrite data still being read.
                MBARRIER_ARRIVE_CLUSTER(MB_EMPTX + s * 8, rank ^ 1);
                MBARRIER_WAIT_PARITY(MB_EMPTX + s * 8, (kk >> 1) & 1);
                issue_fill(kk + 2);
            }
        }
    } else if (tid < 512) {
        // ---------------- consumers: 16 warps, branch-free hot loop --------
        const int w   = wid;          // 0..15
        const int sub = w & 3;        // TMEM subpartition == SMSP
        const int ch  = w >> 2;       // 64-column chunk 0..3
        for (int lt = 0; lt < ntiles; lt++) {
            const int buf  = lt & 1;
            const int q    = pair + lt * NPAIR;
            const int row0 = ((q >> 4) * 2 + rank) * TM;
            const int col0 = (q & 15) * TN;
            const int r    = row0 + sub * 32 + lane;
            const uint32_t dbuf = tmem + buf * 256 + ch * 64;
            float* mdc = s_mdc + buf * 256 + ch * 64;
            int cnt = 0;

            // prefetch diag values BEFORE the result wait (hide LDG latency)
            const float dr  = g_diag[r];
            const float mdr = MARGIN - dr;
            const float m0  = MARGIN - g_diag[col0 + ch * 64 + lane];
            const float m1  = MARGIN - g_diag[col0 + ch * 64 + 32 + lane];

            MBARRIER_WAIT_PARITY(MB_RES + buf * 8, (lt >> 1) & 1);
            TCGEN05_FENCE_AFTER();

            // self-written per warp (each warp reads only what it wrote)
            mdc[lane]      = m0;
            mdc[lane + 32] = m1;

            #pragma unroll 1
            for (int g = 0; g < 2; g++) {
                uint32_t dreg[32];
                TCGEN05_LD_X32(dreg, dbuf + g * 32);
                TCGEN05_WAIT_LD();
                if (g == 1) {
                    TCGEN05_FENCE_BEFORE();
                    if (lane == 0) MBARRIER_ARRIVE(MB_EPI + buf * 8);
                }
                uint32_t tiebits = 0u;
                #pragma unroll
                for (int j = 0; j < 32; j++) {
                    const float sv = __uint_as_float(dreg[j]);
                    const float diff = sv - dr;
                    vt += fmaxf(sv + mdr, 0.f);
                    tv += fmaxf(sv + mdc[g * 32 + j], 0.f);
                    cnt += (diff > EPS) ? 1 : 0;
                    tiebits |= (fabsf(diff) <= EPS) ? (1u << j) : 0u;
                }
                if (tiebits) {   // rare: diagonal element + true near-ties
                    do {
                        const int j = __ffs(tiebits) - 1;
                        tiebits &= tiebits - 1u;
                        const int c = col0 + ch * 64 + g * 32 + j;
                        if (c != r)
                            cnt += (exact_dot(V, T, r, c) > dr) ? 1 : 0;
                    } while (tiebits);
                }
            }
            atomicAdd(&g_cnt[r], cnt);
        }
    }

    __syncthreads();
    if (wid == 16) TCGEN05_DEALLOC(tmem, 512);
    CLUSTER_SYNC();     // no CTA exits while peer multicast may be in flight

#else  // ---------------- fallback: plain fp32 (not selected on GB300) -----
    (void)mVhi; (void)mVlo; (void)mThi; (void)mTlo;
    for (int lt = 0; lt < ntiles; lt++) {
        const int q    = pair + lt * NPAIR;
        const int row0 = ((q >> 4) * 2 + rank) * TM;
        const int col0 = (q & 15) * TN;
        if (tid < 128) {
            const int r = row0 + tid;
            const float dr = g_diag[r];
            int cnt = 0;
            for (int cc = 0; cc < TN; cc++) {
                const int c = col0 + cc;
                if (c == r) { vt += MARGIN; tv += MARGIN; continue; }
                float s = exact_dot(V, T, r, c);
                vt += fmaxf(0.f, MARGIN - dr + s);
                tv += fmaxf(0.f, MARGIN - g_diag[c] + s);
                cnt += (s > dr) ? 1 : 0;
            }
            atomicAdd(&g_cnt[r], cnt);
        }
    }
    __syncthreads();
#endif

    // loss reduction: one double atomic per warp
    #pragma unroll
    for (int off = 16; off > 0; off >>= 1) {
        vt += __shfl_down_sync(0xFFFFFFFFu, vt, off);
        tv += __shfl_down_sync(0xFFFFFFFFu, tv, off);
    }
    if (lane == 0) {
        atomicAdd(&g_vt_sum, (double)vt);
        atomicAdd(&g_tv_sum, (double)tv);
    }

    // ---- last-CTA finalize ----
    __shared__ unsigned s_last;
    __shared__ int rA[512], rB[512], rC[512], rD[512];
    __threadfence();
    __syncthreads();
    if (tid == 0) s_last = (atomicAdd(&g_done, 1u) == (unsigned)(NCTA - 1));
    __syncthreads();
    if (!s_last) return;

    if (tid < 512) {
        int c1 = 0, c5 = 0, c10 = 0, rs = 0;
        for (int i = tid; i < NN; i += 512) {
            int c = g_cnt[i];
            c1  += (c < 1);
            c5  += (c < 5);
            c10 += (c < 10);
            rs  += c;
        }
        rA[tid] = c1; rB[tid] = c5; rC[tid] = c10; rD[tid] = rs;
    }
    __syncthreads();
    for (int s = 256; s > 0; s >>= 1) {
        if (tid < s) {
            rA[tid] += rA[tid + s]; rB[tid] += rB[tid + s];
            rC[tid] += rC[tid + s]; rD[tid] += rD[tid + s];
        }
        __syncthreads();
    }
    if (tid == 0) {
        const double denom = (double)NN * (double)(NN - 1);
        const double diagfix = (double)NN * (double)MARGIN;  // diagonal hinge
        out[0] = (float)((g_vt_sum - diagfix) / denom);
        out[1] = (float)((g_tv_sum - diagfix) / denom);
        out[2] = (float)rA[0] / (float)NN;
        out[3] = (float)rB[0] / (float)NN;
        out[4] = (float)rC[0] / (float)NN;
        out[5] = (float)rD[0] / (float)NN;
    }
}

// ---------------------------------------------------------------------------
typedef CUresult (*EncodeFn)(CUtensorMap*, CUtensorMapDataType, unsigned int,
                             void*, const unsigned long long*,
                             const unsigned long long*, const unsigned int*,
                             const unsigned int*, CUtensorMapInterleave,
                             CUtensorMapSwizzle, CUtensorMapL2promotion,
                             CUtensorMapFloatOOBfill);

static void encode_map(EncodeFn enc, CUtensorMap* m, void* ptr, unsigned rows) {
    unsigned long long dims[2]    = {DD, NN};
    unsigned long long strides[1] = {DD * sizeof(__nv_bfloat16)};
    unsigned int box[2]           = {64, rows};
    unsigned int es[2]            = {1, 1};
    enc(m, CU_TENSOR_MAP_DATA_TYPE_BFLOAT16, 2, ptr, dims, strides, box, es,
        CU_TENSOR_MAP_INTERLEAVE_NONE, CU_TENSOR_MAP_SWIZZLE_128B,
        CU_TENSOR_MAP_L2_PROMOTION_L2_128B, CU_TENSOR_MAP_FLOAT_OOB_FILL_NONE);
}

extern "C" void kernel_launch(void* const* d_in, const int* in_sizes, int n_in,
                              void* d_out, int out_size) {
    (void)in_sizes; (void)n_in; (void)out_size;
    const float* V = (const float*)d_in[0];
    const float* T = (const float*)d_in[1];
    float* out = (float*)d_out;

    void *pVhi, *pVlo, *pThi, *pTlo;
    cudaGetSymbolAddress(&pVhi, g_Vhi);
    cudaGetSymbolAddress(&pVlo, g_Vlo);
    cudaGetSymbolAddress(&pThi, g_Thi);
    cudaGetSymbolAddress(&pTlo, g_Tlo);

    void* sym = nullptr;
    cudaDriverEntryPointQueryResult qr;
    cudaGetDriverEntryPointByVersion("cuTensorMapEncodeTiled", &sym, 12000,
                                     cudaEnableDefault, &qr);
    EncodeFn enc = (EncodeFn)sym;

    CUtensorMap mVhi, mVlo, mThi, mTlo;
    encode_map(enc, &mVhi, pVhi, TM);   // A tiles: 128 rows
    encode_map(enc, &mVlo, pVlo, TM);
    encode_map(enc, &mThi, pThi, TN);   // B tiles: 256 rows
    encode_map(enc, &mTlo, pTlo, TN);

    cudaFuncSetAttribute(gemm_tc_kernel,
                         cudaFuncAttributeMaxDynamicSharedMemorySize, SMEM_DYN);

    init_kernel<<<NN * 32 / 256, 256>>>(V, T);
    gemm_tc_kernel<<<NCTA, NTHREADS, SMEM_DYN>>>(
        mVhi, mVlo, mThi, mTlo, V, T, out);
}